// round 1
// baseline (speedup 1.0000x reference)
#include <cuda_runtime.h>

#define BLOCK 256
#define LOG_CLAMP (-100.0f)
#define HDELTA 0.04f
#define MAX_B 32768

// Per-row partial losses (scratch; no dynamic allocation allowed)
__device__ float g_ce[MAX_B];
__device__ float g_hu[MAX_B];

// log1p(-p) for p in [0, ~0.1): 5-term series, error < p^6/6 (~1e-8 at p=0.0625).
// Falls back to log1pf for larger p (rare / never for this data distribution).
__device__ __forceinline__ float log1mp(float p) {
    if (p > 0.0625f) {
        return fmaxf(log1pf(-p), LOG_CLAMP);
    }
    // -(p + p^2/2 + p^3/3 + p^4/4 + p^5/5)
    return -p * (1.0f + p * (0.5f + p * (0.33333333f + p * (0.25f + p * 0.2f))));
}

// Block-wide sum over 256 threads (8 warps). Safe for back-to-back reuse of sbuf.
__device__ __forceinline__ float block_sum(float v, float* sbuf, int lane, int warp) {
    #pragma unroll
    for (int o = 16; o; o >>= 1) v += __shfl_down_sync(0xffffffffu, v, o);
    if (lane == 0) sbuf[warp] = v;
    __syncthreads();
    float r;
    if (warp == 0) {
        float x = (lane < 8) ? sbuf[lane] : 0.0f;
        #pragma unroll
        for (int o = 4; o; o >>= 1) x += __shfl_down_sync(0xffffffffu, x, o);
        if (lane == 0) sbuf[0] = x;
    }
    __syncthreads();
    r = sbuf[0];
    __syncthreads();   // protect sbuf before next reuse
    return r;
}

__device__ __forceinline__ float block_max(float v, float* sbuf, int lane, int warp) {
    #pragma unroll
    for (int o = 16; o; o >>= 1) v = fmaxf(v, __shfl_down_sync(0xffffffffu, v, o));
    if (lane == 0) sbuf[warp] = v;
    __syncthreads();
    float r;
    if (warp == 0) {
        float x = (lane < 8) ? sbuf[lane] : -3.4e38f;
        #pragma unroll
        for (int o = 4; o; o >>= 1) x = fmaxf(x, __shfl_down_sync(0xffffffffu, x, o));
        if (lane == 0) sbuf[0] = x;
    }
    __syncthreads();
    r = sbuf[0];
    __syncthreads();
    return r;
}

__device__ __forceinline__ float huber1(float x) {
    float ax = fabsf(x);
    float quad = 0.5f * x * x;
    float lin  = HDELTA * (ax - 0.5f * HDELTA);
    return (ax <= HDELTA) ? quad : lin;
}

__global__ void __launch_bounds__(BLOCK)
loss_row_kernel(const float* __restrict__ anchors,
                const float* __restrict__ offsets,
                const float* __restrict__ conf,
                const float* __restrict__ gt,
                int N)
{
    const int b    = blockIdx.x;
    const int t    = threadIdx.x;
    const int lane = t & 31;
    const int warp = t >> 5;

    __shared__ float sbuf[8];
    __shared__ float swv[8];
    __shared__ int   swi[8];
    __shared__ int   s_k;

    const float2 g = ((const float2*)gt)[b];
    const float* __restrict__ arow = anchors + (size_t)b * (size_t)N * 2u;
    const float* __restrict__ crow = conf    + (size_t)b * (size_t)N;

    // ------------------------------------------------------------------
    // Pass 1: argmin of squared distance (sqrt is monotone -> skip it).
    // Tie-break to the LOWEST index, matching jnp.argmin.
    // ------------------------------------------------------------------
    float best = 3.4e38f;
    int   bidx = 0;
    const float2* a2 = (const float2*)arow;
    for (int i = t; i < N; i += BLOCK) {
        float2 a = a2[i];
        float dx = a.x - g.x, dy = a.y - g.y;
        float d  = dx * dx + dy * dy;
        if (d < best || (d == best && i < bidx)) { best = d; bidx = i; }
    }
    #pragma unroll
    for (int o = 16; o; o >>= 1) {
        float ov = __shfl_down_sync(0xffffffffu, best, o);
        int   oi = __shfl_down_sync(0xffffffffu, bidx, o);
        if (ov < best || (ov == best && oi < bidx)) { best = ov; bidx = oi; }
    }
    if (lane == 0) { swv[warp] = best; swi[warp] = bidx; }
    __syncthreads();
    if (t == 0) {
        float bb = swv[0]; int bi = swi[0];
        #pragma unroll
        for (int w = 1; w < 8; w++) {
            if (swv[w] < bb || (swv[w] == bb && swi[w] < bi)) { bb = swv[w]; bi = swi[w]; }
        }
        s_k = bi;
    }
    __syncthreads();

    // ------------------------------------------------------------------
    // Pass 2: softmax stats + sum of log1p(-p) terms.
    // Fast path: N == 2048 -> cache confidences (8/thread) in registers.
    // ------------------------------------------------------------------
    float m, S, T;
    if (N == 2048) {
        float c[8], e[8];
        const float4* c4 = (const float4*)crow;
        float4 v0 = c4[t];
        float4 v1 = c4[t + 256];
        c[0]=v0.x; c[1]=v0.y; c[2]=v0.z; c[3]=v0.w;
        c[4]=v1.x; c[5]=v1.y; c[6]=v1.z; c[7]=v1.w;

        float lm = -3.4e38f;
        #pragma unroll
        for (int i = 0; i < 8; i++) lm = fmaxf(lm, c[i]);
        m = block_max(lm, sbuf, lane, warp);

        float ls = 0.0f;
        #pragma unroll
        for (int i = 0; i < 8; i++) { e[i] = __expf(c[i] - m); ls += e[i]; }
        S = block_sum(ls, sbuf, lane, warp);

        float invS = __frcp_rn(S);
        float lt = 0.0f;
        #pragma unroll
        for (int i = 0; i < 8; i++) lt += log1mp(e[i] * invS);
        T = block_sum(lt, sbuf, lane, warp);
    } else {
        // Generic fallback: three streaming passes (L1/L2-hot after first).
        float lm = -3.4e38f;
        for (int i = t; i < N; i += BLOCK) lm = fmaxf(lm, __ldg(crow + i));
        m = block_max(lm, sbuf, lane, warp);

        float ls = 0.0f;
        for (int i = t; i < N; i += BLOCK) ls += __expf(__ldg(crow + i) - m);
        S = block_sum(ls, sbuf, lane, warp);

        float invS = __frcp_rn(S);
        float lt = 0.0f;
        for (int i = t; i < N; i += BLOCK) lt += log1mp(__expf(__ldg(crow + i) - m) * invS);
        T = block_sum(lt, sbuf, lane, warp);
    }

    // ------------------------------------------------------------------
    // Thread 0: fix up the winning index term + Huber on gathered pair.
    // ------------------------------------------------------------------
    if (t == 0) {
        const int k = s_k;
        float ck   = __ldg(crow + k);
        float logS = __logf(S);
        float invS = __frcp_rn(S);
        float pk   = __expf(ck - m) * invS;
        float logpk = fmaxf(ck - m - logS, LOG_CLAMP);
        float tk    = log1mp(pk);
        float ce    = -(logpk + (T - tk));

        float2 ak = ((const float2*)arow)[k];
        const float* orow = offsets + (size_t)b * (size_t)N * 2u;
        float2 ok = ((const float2*)orow)[k];
        // gt_offset = gt - closest_anchor; x = closest_offset - gt_offset
        float x0 = ok.x - (g.x - ak.x);
        float x1 = ok.y - (g.y - ak.y);
        float hu = huber1(x0) + huber1(x1);

        g_ce[b] = ce;
        g_hu[b] = hu;
    }
}

// Deterministic fixed-order final reduction. out = {total, ce, huber}.
__global__ void __launch_bounds__(BLOCK)
final_reduce_kernel(float* __restrict__ out, int B)
{
    __shared__ float sc[BLOCK];
    __shared__ float sh[BLOCK];
    int t = threadIdx.x;
    float ce = 0.0f, hu = 0.0f;
    for (int i = t; i < B; i += BLOCK) { ce += g_ce[i]; hu += g_hu[i]; }
    sc[t] = ce; sh[t] = hu;
    __syncthreads();
    #pragma unroll
    for (int s = BLOCK / 2; s; s >>= 1) {
        if (t < s) { sc[t] += sc[t + s]; sh[t] += sh[t + s]; }
        __syncthreads();
    }
    if (t == 0) {
        out[1] = sc[0];
        out[2] = sh[0];
        out[0] = sc[0] + sh[0];
    }
}

extern "C" void kernel_launch(void* const* d_in, const int* in_sizes, int n_in,
                              void* d_out, int out_size)
{
    const float* anchors = (const float*)d_in[0];   // (B, N, 2)
    const float* offsets = (const float*)d_in[1];   // (B, N, 2)
    const float* conf    = (const float*)d_in[2];   // (B, N)
    const float* gt      = (const float*)d_in[3];   // (B, 2)

    int B = in_sizes[3] / 2;
    int N = (B > 0) ? (in_sizes[2] / B) : 0;
    if (B <= 0 || N <= 0) return;
    if (B > MAX_B) B = MAX_B;   // scratch capacity guard (actual B = 8192)

    loss_row_kernel<<<B, BLOCK>>>(anchors, offsets, conf, gt, N);
    final_reduce_kernel<<<1, BLOCK>>>((float*)d_out, B);
}

// round 2
// speedup vs baseline: 1.1471x; 1.1471x over previous
#include <cuda_runtime.h>

#define BLOCK 256
#define LOG_CLAMP (-100.0f)
#define HDELTA 0.04f
#define FXSCALE 16777216.0   // 2^24 fixed-point scale

// Deterministic cross-block accumulation: integer adds are associative,
// so the result is bitwise identical regardless of block arrival order.
__device__ unsigned long long g_ce_acc = 0ULL;
__device__ unsigned long long g_hu_acc = 0ULL;
__device__ unsigned int       g_done   = 0u;

// log1p(-p) for p in [0, ~0.1): 5-term series, |err| < p^6/6.
// Data distribution: p = softmax of 2048 N(0,1) values => p <= ~0.012,
// so the series path is always taken; fallback kept for safety.
__device__ __forceinline__ float log1mp(float p) {
    if (p > 0.0625f) return fmaxf(log1pf(-p), LOG_CLAMP);
    return -p * (1.0f + p * (0.5f + p * (0.33333333f + p * (0.25f + p * 0.2f))));
}

__device__ __forceinline__ float block_sum(float v, float* sbuf, int lane, int warp) {
    #pragma unroll
    for (int o = 16; o; o >>= 1) v += __shfl_down_sync(0xffffffffu, v, o);
    if (lane == 0) sbuf[warp] = v;
    __syncthreads();
    if (warp == 0) {
        float x = (lane < 8) ? sbuf[lane] : 0.0f;
        #pragma unroll
        for (int o = 4; o; o >>= 1) x += __shfl_down_sync(0xffffffffu, x, o);
        if (lane == 0) sbuf[0] = x;
    }
    __syncthreads();
    float r = sbuf[0];
    __syncthreads();
    return r;
}

__device__ __forceinline__ float block_max(float v, float* sbuf, int lane, int warp) {
    #pragma unroll
    for (int o = 16; o; o >>= 1) v = fmaxf(v, __shfl_down_sync(0xffffffffu, v, o));
    if (lane == 0) sbuf[warp] = v;
    __syncthreads();
    if (warp == 0) {
        float x = (lane < 8) ? sbuf[lane] : -3.4e38f;
        #pragma unroll
        for (int o = 4; o; o >>= 1) x = fmaxf(x, __shfl_down_sync(0xffffffffu, x, o));
        if (lane == 0) sbuf[0] = x;
    }
    __syncthreads();
    float r = sbuf[0];
    __syncthreads();
    return r;
}

__device__ __forceinline__ float huber1(float x) {
    float ax = fabsf(x);
    float quad = 0.5f * x * x;
    float lin  = HDELTA * (ax - 0.5f * HDELTA);
    return (ax <= HDELTA) ? quad : lin;
}

__global__ void __launch_bounds__(BLOCK)
loss_kernel(const float* __restrict__ anchors,
            const float* __restrict__ offsets,
            const float* __restrict__ conf,
            const float* __restrict__ gt,
            int N,
            float* __restrict__ out)
{
    const int b    = blockIdx.x;
    const int t    = threadIdx.x;
    const int lane = t & 31;
    const int warp = t >> 5;

    __shared__ float sbuf[8];
    __shared__ float swv[8];
    __shared__ int   swi[8];
    __shared__ int   s_k;

    const float2 g = ((const float2*)gt)[b];
    const float* __restrict__ arow = anchors + (size_t)b * (size_t)N * 2u;
    const float* __restrict__ crow = conf    + (size_t)b * (size_t)N;

    float m, S, T;      // softmax max, sum-exp, sum of log1p(-p)
    float best = 3.4e38f;
    int   bidx = 0;

    if (N == 2048) {
        // ---- Prefetch confidences (2x LDG.128) so they overlap the anchor pass.
        const float4* c4 = (const float4*)crow;
        float4 cv0 = c4[t];
        float4 cv1 = c4[t + 256];

        // ---- Argmin over squared distance: 4x LDG.128 (2 anchors each),
        //      fully unrolled, all loads front-batched for MLP.
        const float4* a4 = (const float4*)arow;
        #pragma unroll
        for (int j = 0; j < 4; j++) {
            int i4 = t + j * 256;          // float4 index = anchor pair (2*i4, 2*i4+1)
            float4 a = a4[i4];
            float dx0 = a.x - g.x, dy0 = a.y - g.y;
            float dx1 = a.z - g.x, dy1 = a.w - g.y;
            float d0 = dx0 * dx0 + dy0 * dy0;
            float d1 = dx1 * dx1 + dy1 * dy1;
            // ascending indices within a thread: strict < keeps first occurrence
            if (d0 < best) { best = d0; bidx = 2 * i4; }
            if (d1 < best) { best = d1; bidx = 2 * i4 + 1; }
        }

        // ---- Softmax stats entirely from registers.
        float c[8];
        c[0]=cv0.x; c[1]=cv0.y; c[2]=cv0.z; c[3]=cv0.w;
        c[4]=cv1.x; c[5]=cv1.y; c[6]=cv1.z; c[7]=cv1.w;

        float lm = -3.4e38f;
        #pragma unroll
        for (int i = 0; i < 8; i++) lm = fmaxf(lm, c[i]);
        m = block_max(lm, sbuf, lane, warp);

        float e[8], ls = 0.0f;
        #pragma unroll
        for (int i = 0; i < 8; i++) { e[i] = __expf(c[i] - m); ls += e[i]; }
        S = block_sum(ls, sbuf, lane, warp);

        float invS = __frcp_rn(S);
        float lt = 0.0f;
        #pragma unroll
        for (int i = 0; i < 8; i++) lt += log1mp(e[i] * invS);
        T = block_sum(lt, sbuf, lane, warp);
    } else {
        // Generic fallback (streaming).
        const float2* a2 = (const float2*)arow;
        for (int i = t; i < N; i += BLOCK) {
            float2 a = a2[i];
            float dx = a.x - g.x, dy = a.y - g.y;
            float d  = dx * dx + dy * dy;
            if (d < best || (d == best && i < bidx)) { best = d; bidx = i; }
        }
        float lm = -3.4e38f;
        for (int i = t; i < N; i += BLOCK) lm = fmaxf(lm, __ldg(crow + i));
        m = block_max(lm, sbuf, lane, warp);
        float ls = 0.0f;
        for (int i = t; i < N; i += BLOCK) ls += __expf(__ldg(crow + i) - m);
        S = block_sum(ls, sbuf, lane, warp);
        float invS = __frcp_rn(S);
        float lt = 0.0f;
        for (int i = t; i < N; i += BLOCK) lt += log1mp(__expf(__ldg(crow + i) - m) * invS);
        T = block_sum(lt, sbuf, lane, warp);
    }

    // ---- Block argmin combine (with cross-thread lowest-index tie-break).
    #pragma unroll
    for (int o = 16; o; o >>= 1) {
        float ov = __shfl_down_sync(0xffffffffu, best, o);
        int   oi = __shfl_down_sync(0xffffffffu, bidx, o);
        if (ov < best || (ov == best && oi < bidx)) { best = ov; bidx = oi; }
    }
    if (lane == 0) { swv[warp] = best; swi[warp] = bidx; }
    __syncthreads();
    if (t == 0) {
        float bb = swv[0]; int bi = swi[0];
        #pragma unroll
        for (int w = 1; w < 8; w++) {
            if (swv[w] < bb || (swv[w] == bb && swi[w] < bi)) { bb = swv[w]; bi = swi[w]; }
        }
        s_k = bi;
    }
    __syncthreads();

    // ---- Thread 0: winning-index CE fixup, Huber pair, fixed-point atomics.
    if (t == 0) {
        const int k = s_k;
        float ck    = __ldg(crow + k);
        float logS  = __logf(S);
        float pk    = __expf(ck - m) * __frcp_rn(S);
        float logpk = fmaxf(ck - m - logS, LOG_CLAMP);
        float tk    = log1mp(pk);
        float ce    = -(logpk + (T - tk));

        float2 ak = ((const float2*)arow)[k];
        const float* orow = offsets + (size_t)b * (size_t)N * 2u;
        float2 ok = ((const float2*)orow)[k];
        float x0 = ok.x - (g.x - ak.x);
        float x1 = ok.y - (g.y - ak.y);
        float hu = huber1(x0) + huber1(x1);

        unsigned long long cei =
            (unsigned long long)(long long)__double2ll_rn((double)ce * FXSCALE);
        unsigned long long hui =
            (unsigned long long)(long long)__double2ll_rn((double)hu * FXSCALE);
        atomicAdd(&g_ce_acc, cei);
        atomicAdd(&g_hu_acc, hui);

        __threadfence();
        unsigned int old = atomicAdd(&g_done, 1u);
        if (old == gridDim.x - 1u) {
            // All blocks' atomics are globally visible (fence before counter).
            long long cs = (long long)atomicAdd(&g_ce_acc, 0ULL);
            long long hs = (long long)atomicAdd(&g_hu_acc, 0ULL);
            float cef = (float)((double)cs * (1.0 / FXSCALE));
            float huf = (float)((double)hs * (1.0 / FXSCALE));
            out[0] = cef + huf;
            out[1] = cef;
            out[2] = huf;
            // Reset for the next (graph-replayed) call: deterministic state.
            g_ce_acc = 0ULL;
            g_hu_acc = 0ULL;
            __threadfence();
            g_done = 0u;
        }
    }
}

extern "C" void kernel_launch(void* const* d_in, const int* in_sizes, int n_in,
                              void* d_out, int out_size)
{
    const float* anchors = (const float*)d_in[0];   // (B, N, 2)
    const float* offsets = (const float*)d_in[1];   // (B, N, 2)
    const float* conf    = (const float*)d_in[2];   // (B, N)
    const float* gt      = (const float*)d_in[3];   // (B, 2)

    int B = in_sizes[3] / 2;
    int N = (B > 0) ? (in_sizes[2] / B) : 0;
    if (B <= 0 || N <= 0) return;

    loss_kernel<<<B, BLOCK>>>(anchors, offsets, conf, gt, N, (float*)d_out);
}